// round 1
// baseline (speedup 1.0000x reference)
#include <cuda_runtime.h>
#include <cuda_bf16.h>

// Problem shapes (fixed instance): B=2048, L=196, M=16, NBL=10.
// Dims are re-derived from in_sizes; static scratch sized with headroom.

#define MAXSITES 256          // >= L-2 (=194)
#define MAXB     4096         // >= B   (=2048)

// Packed site tensors: Pack[s][m][n] = float2{A0[m][n], A1[m][n]}
// PackL: forward order (sites 0..L-3), used by left chains.
// PackR: reversed + transposed, so the right sweep becomes the same
//        "v_new[n] = sum_m v[m]*B[m][n]" forward form.
__device__ float2 g_PackL[MAXSITES * 16 * 16];
__device__ float2 g_PackR[MAXSITES * 16 * 16];
__device__ float  g_left [MAXB * 16];
__device__ float  g_right[MAXB * 16];

// ---------------------------------------------------------------------------
// Kernel 1: repack A_mid (Lm2, 2, 16, 16) into interleaved float2 layouts.
// ---------------------------------------------------------------------------
__global__ void prep_kernel(const float* __restrict__ A_mid, int Lm2) {
    int e = blockIdx.x * blockDim.x + threadIdx.x;
    int total = Lm2 * 256;
    if (e >= total) return;
    int s  = e >> 8;          // site
    int mn = e & 255;         // m*16+n
    int m  = mn >> 4;
    int n  = mn & 15;
    float a0 = A_mid[s * 512 + mn];        // A_mid[s][0][m][n]
    float a1 = A_mid[s * 512 + 256 + mn];  // A_mid[s][1][m][n]
    g_PackL[s * 256 + mn] = make_float2(a0, a1);
    // right chain, step t = (Lm2-1) - s, needs transposed matrix
    g_PackR[(Lm2 - 1 - s) * 256 + n * 16 + m] = make_float2(a0, a1);
}

// ---------------------------------------------------------------------------
// Kernel 2: chain contraction. 4 chains per warp.
//   lane = 0..31 ; n = lane&15 (output component) ; half = lane>>4
//   half 0 handles chains sb+0, sb+1 ; half 1 handles sb+2, sb+3
//   v[m] broadcast via width-16 shuffle.
// ---------------------------------------------------------------------------
__global__ void __launch_bounds__(256)
chain_kernel(const float* __restrict__ inputs,
             const float* __restrict__ A_left,
             const float* __restrict__ A_right,
             const int*   __restrict__ pos_ptr,
             int B, int L) {
    int tid  = blockIdx.x * blockDim.x + threadIdx.x;
    int w    = tid >> 5;
    int lane = tid & 31;
    int n    = lane & 15;
    int half = lane >> 4;

    int pos = __ldg(pos_ptr);
    int warpsPerSide = B >> 2;           // B/4 warps per direction
    bool isLeft = (w < warpsPerSide);
    int sb = (isLeft ? w : w - warpsPerSide) << 2;   // first chain (=sample) of warp
    int c0 = sb + 2 * half;
    int c1 = c0 + 1;
    int nsites = isLeft ? pos : (L - 2 - pos);

    const float2* pack  = isLeft ? g_PackL : g_PackR;
    const float*  seedA = isLeft ? A_left  : A_right;
    const float2* in2   = (const float2*)inputs;     // (B, L) of float2
    int seedSite = isLeft ? 0 : (L - 1);

    // seed vectors: v[n] = x0*Aseed[0][n] + x1*Aseed[1][n]
    float a0n = __ldg(seedA + n);
    float a1n = __ldg(seedA + 16 + n);
    float2 xs0 = in2[c0 * L + seedSite];
    float2 xs1 = in2[c1 * L + seedSite];
    float va = fmaf(xs0.y, a1n, xs0.x * a0n);
    float vb = fmaf(xs1.y, a1n, xs1.x * a0n);

    for (int s = 0; s < nsites; ++s) {
        int xsite = isLeft ? (1 + s) : (L - 2 - s);
        float2 xa = in2[c0 * L + xsite];
        float2 xb = in2[c1 * L + xsite];
        const float2* mp = pack + s * 256 + n;

        float acc0a = 0.f, acc1a = 0.f, acc0b = 0.f, acc1b = 0.f;
#pragma unroll
        for (int m = 0; m < 16; ++m) {
            float2 ap = __ldg(mp + m * 16);
            float vam = __shfl_sync(0xffffffffu, va, m, 16);
            float vbm = __shfl_sync(0xffffffffu, vb, m, 16);
            acc0a = fmaf(vam, ap.x, acc0a);
            acc1a = fmaf(vam, ap.y, acc1a);
            acc0b = fmaf(vbm, ap.x, acc0b);
            acc1b = fmaf(vbm, ap.y, acc1b);
        }
        va = fmaf(xa.x, acc0a, xa.y * acc1a);
        vb = fmaf(xb.x, acc0b, xb.y * acc1b);
    }

    float* out = isLeft ? g_left : g_right;
    out[c0 * 16 + n] = va;
    out[c1 * 16 + n] = vb;
}

// ---------------------------------------------------------------------------
// Kernel 3: out[b][l] = sum_{m,n} left[b][m] * T[m][n][l] * right[b][n]
// one thread per (b,l)
// ---------------------------------------------------------------------------
__global__ void combine_kernel(const float* __restrict__ T,
                               float* __restrict__ out,
                               int B, int NBL) {
    int idx = blockIdx.x * blockDim.x + threadIdx.x;
    if (idx >= B * NBL) return;
    int b = idx / NBL;
    int l = idx - b * NBL;

    float rv[16];
#pragma unroll
    for (int k = 0; k < 16; ++k) rv[k] = g_right[b * 16 + k];

    float s = 0.f;
#pragma unroll
    for (int m = 0; m < 16; ++m) {
        float t = 0.f;
#pragma unroll
        for (int k = 0; k < 16; ++k)
            t = fmaf(__ldg(T + (m * 16 + k) * NBL + l), rv[k], t);
        s = fmaf(g_left[b * 16 + m], t, s);
    }
    out[idx] = s;
}

// ---------------------------------------------------------------------------
extern "C" void kernel_launch(void* const* d_in, const int* in_sizes, int n_in,
                              void* d_out, int out_size) {
    const float* inputs  = (const float*)d_in[0];
    const float* A_left  = (const float*)d_in[1];
    const float* A_mid   = (const float*)d_in[2];
    const float* A_right = (const float*)d_in[3];
    const float* T_out   = (const float*)d_in[4];
    const int*   pos     = (const int*)d_in[5];

    int Lm2 = in_sizes[2] / 512;          // (L-2), = 194
    int L   = Lm2 + 2;                    // 196
    int B   = in_sizes[0] / (2 * L);      // 2048
    int NBL = in_sizes[4] / 256;          // 10

    // 1) repack A_mid
    {
        int total = Lm2 * 256;
        prep_kernel<<<(total + 255) / 256, 256>>>(A_mid, Lm2);
    }
    // 2) chains: B/2 warps total (B/4 left-warps + B/4 right-warps), 4 chains/warp
    {
        int warps   = B / 2;              // 1024
        int threads = warps * 32;         // 32768
        chain_kernel<<<threads / 256, 256>>>(inputs, A_left, A_right, pos, B, L);
    }
    // 3) combine
    {
        int total = B * NBL;
        combine_kernel<<<(total + 255) / 256, 256>>>(T_out, (float*)d_out, B, NBL);
    }
}

// round 2
// speedup vs baseline: 2.6480x; 2.6480x over previous
#include <cuda_runtime.h>

// Shapes (this instance): B=2048, L=196, M=16, NBL=10. Re-derived from in_sizes.
#define MAXSITES 256          // >= L-2 (=194)
#define MAXB     4096         // >= B   (=2048)

// Packed site tensors: Pack[s][m*16+n] = float2{A0[m][n], A1[m][n]}
// PackL: forward order. PackR: reversed + transposed so the right sweep is the
// same forward "v_new[n] = sum_m v[m]*M[m][n]" form.
__device__ float2 g_PackL[MAXSITES * 256];
__device__ float2 g_PackR[MAXSITES * 256];
__device__ float  g_left [MAXB * 16];
__device__ float  g_right[MAXB * 16];

// ---------------------------------------------------------------------------
// cp.async helpers
// ---------------------------------------------------------------------------
__device__ __forceinline__ void cpasync16(unsigned dst, const void* src) {
    asm volatile("cp.async.cg.shared.global [%0], [%1], 16;\n"
                 :: "r"(dst), "l"(src) : "memory");
}
__device__ __forceinline__ void cpcommit() {
    asm volatile("cp.async.commit_group;\n" ::: "memory");
}
template<int N> __device__ __forceinline__ void cpwait() {
    asm volatile("cp.async.wait_group %0;\n" :: "n"(N) : "memory");
}

// ---------------------------------------------------------------------------
// Kernel 1: repack A_mid (Lm2, 2, 16, 16). One block (256 thr) per site.
// PackL write coalesced directly; PackR via smem transpose (coalesced store).
// ---------------------------------------------------------------------------
__global__ void __launch_bounds__(256)
prep_kernel(const float* __restrict__ A_mid, int Lm2) {
    __shared__ float2 sm[16 * 17];
    int s = blockIdx.x;
    int t = threadIdx.x;               // 0..255 = m*16+n
    float a0 = A_mid[s * 512 + t];
    float a1 = A_mid[s * 512 + 256 + t];
    float2 v = make_float2(a0, a1);
    g_PackL[s * 256 + t] = v;
    int m = t >> 4, n = t & 15;
    sm[m * 17 + n] = v;
    __syncthreads();
    // output index t = n2*16 + m2 -> read sm[m2][n2]
    int n2 = t >> 4, m2 = t & 15;
    g_PackR[(Lm2 - 1 - s) * 256 + t] = sm[m2 * 17 + n2];
}

// ---------------------------------------------------------------------------
// Kernel 2: lockstep chain contraction.
// Block = 128 threads (4 warps) = 16 chains, all same direction.
// Per site: cp.async-staged matrix (3-deep ring), one __syncthreads,
// v exchanged via padded smem (no shuffles).
//   lane: n = lane&15 (output component), half = lane>>4 selects chain pair.
// ---------------------------------------------------------------------------
__global__ void __launch_bounds__(128)
chain_kernel(const float* __restrict__ inputs,
             const float* __restrict__ A_left,
             const float* __restrict__ A_right,
             const int*   __restrict__ pos_ptr,
             int B, int L) {
    __shared__ float2 matBuf[3][256];      // 3 x 2KB ring
    __shared__ float  vBuf[16 * 20];       // 16 chains, stride 20 (pad)

    int tid  = threadIdx.x;
    int w    = tid >> 5;
    int lane = tid & 31;
    int n    = lane & 15;
    int half = lane >> 4;

    int pos = __ldg(pos_ptr);
    int nLeftBlocks = B >> 4;              // B/16
    bool isLeft = (blockIdx.x < (unsigned)nLeftBlocks);
    int blk   = isLeft ? blockIdx.x : blockIdx.x - nLeftBlocks;
    int cbase = blk * 16;
    int lc0 = w * 4 + half * 2;
    int lc1 = lc0 + 1;
    int c0 = cbase + lc0, c1 = cbase + lc1;
    int nsites = isLeft ? pos : (L - 2 - pos);

    const float2* pack  = isLeft ? g_PackL : g_PackR;
    const float*  seedA = isLeft ? A_left  : A_right;
    const float2* in2   = (const float2*)inputs;   // (B, L) float2
    int seedSite = isLeft ? 0 : (L - 1);

    // seed: v[n] = x0*Aseed[0][n] + x1*Aseed[1][n]
    float a0n = __ldg(seedA + n);
    float a1n = __ldg(seedA + 16 + n);
    float2 xs0 = in2[c0 * L + seedSite];
    float2 xs1 = in2[c1 * L + seedSite];
    float va = fmaf(xs0.y, a1n, xs0.x * a0n);
    float vb = fmaf(xs1.y, a1n, xs1.x * a0n);
    vBuf[lc0 * 20 + n] = va;
    vBuf[lc1 * 20 + n] = vb;

    unsigned smemMat0 = (unsigned)__cvta_generic_to_shared(&matBuf[0][0]);

    // prologue: stage sites 0,1
    if (nsites > 0) {
        cpasync16(smemMat0 + 0 * 2048 + tid * 16,
                  (const char*)(pack) + tid * 16);
        cpcommit();
    }
    if (nsites > 1) {
        cpasync16(smemMat0 + 1 * 2048 + tid * 16,
                  (const char*)(pack + 256) + tid * 16);
        cpcommit();
    }

    int stage = 0;                          // = s % 3
    int stage2 = 2;                         // = (s+2) % 3
    for (int s = 0; s < nsites; ++s) {
        cpwait<1>();                        // matrix for site s resident
        __syncthreads();                    // v(s-1) stored; old buffer free

        if (s + 2 < nsites) {
            cpasync16(smemMat0 + stage2 * 2048 + tid * 16,
                      (const char*)(pack + (s + 2) * 256) + tid * 16);
            cpcommit();
        }

        // load v vectors (broadcast LDS.128 within each half-warp)
        float va_[16], vb_[16];
        {
            const float4* p = (const float4*)(vBuf + lc0 * 20);
            float4 t0 = p[0], t1 = p[1], t2 = p[2], t3 = p[3];
            va_[0]=t0.x; va_[1]=t0.y; va_[2]=t0.z; va_[3]=t0.w;
            va_[4]=t1.x; va_[5]=t1.y; va_[6]=t1.z; va_[7]=t1.w;
            va_[8]=t2.x; va_[9]=t2.y; va_[10]=t2.z; va_[11]=t2.w;
            va_[12]=t3.x; va_[13]=t3.y; va_[14]=t3.z; va_[15]=t3.w;
        }
        {
            const float4* p = (const float4*)(vBuf + lc1 * 20);
            float4 t0 = p[0], t1 = p[1], t2 = p[2], t3 = p[3];
            vb_[0]=t0.x; vb_[1]=t0.y; vb_[2]=t0.z; vb_[3]=t0.w;
            vb_[4]=t1.x; vb_[5]=t1.y; vb_[6]=t1.z; vb_[7]=t1.w;
            vb_[8]=t2.x; vb_[9]=t2.y; vb_[10]=t2.z; vb_[11]=t2.w;
            vb_[12]=t3.x; vb_[13]=t3.y; vb_[14]=t3.z; vb_[15]=t3.w;
        }

        int xsite = isLeft ? (1 + s) : (L - 2 - s);
        float2 xa = in2[c0 * L + xsite];
        float2 xb = in2[c1 * L + xsite];

        const float2* mat = matBuf[stage];
        float p0a=0.f,p1a=0.f,p0b=0.f,p1b=0.f;   // m = 0..7
        float q0a=0.f,q1a=0.f,q0b=0.f,q1b=0.f;   // m = 8..15
#pragma unroll
        for (int m = 0; m < 8; ++m) {
            float2 ap = mat[m * 16 + n];
            p0a = fmaf(va_[m], ap.x, p0a);
            p1a = fmaf(va_[m], ap.y, p1a);
            p0b = fmaf(vb_[m], ap.x, p0b);
            p1b = fmaf(vb_[m], ap.y, p1b);
        }
#pragma unroll
        for (int m = 8; m < 16; ++m) {
            float2 ap = mat[m * 16 + n];
            q0a = fmaf(va_[m], ap.x, q0a);
            q1a = fmaf(va_[m], ap.y, q1a);
            q0b = fmaf(vb_[m], ap.x, q0b);
            q1b = fmaf(vb_[m], ap.y, q1b);
        }
        float s1a = p1a + q1a, s1b = p1b + q1b;
        va = fmaf(xa.x, p0a + q0a, xa.y * s1a);
        vb = fmaf(xb.x, p0b + q0b, xb.y * s1b);

        vBuf[lc0 * 20 + n] = va;
        vBuf[lc1 * 20 + n] = vb;

        stage  = (stage  == 2) ? 0 : stage  + 1;
        stage2 = (stage2 == 2) ? 0 : stage2 + 1;
    }

    float* out = isLeft ? g_left : g_right;
    out[c0 * 16 + n] = va;
    out[c1 * 16 + n] = vb;
}

// ---------------------------------------------------------------------------
// Kernel 3: out[b][l] = sum_{m,k} left[b][m] * T[m][k][l] * right[b][k]
// T cached in smem; one thread per (b,l).
// ---------------------------------------------------------------------------
__global__ void __launch_bounds__(256)
combine_kernel(const float* __restrict__ T,
               float* __restrict__ out,
               int B, int NBL) {
    __shared__ float sT[4096];            // >= 16*16*NBL (NBL<=16)
    int tid = threadIdx.x;
    int tElems = 256 * NBL;
    for (int i = tid; i < tElems; i += blockDim.x) sT[i] = T[i];
    __syncthreads();

    int idx = blockIdx.x * blockDim.x + tid;
    if (idx >= B * NBL) return;
    int b = idx / NBL;
    int l = idx - b * NBL;

    float lv[16], rv[16];
#pragma unroll
    for (int k = 0; k < 16; ++k) {
        lv[k] = g_left [b * 16 + k];
        rv[k] = g_right[b * 16 + k];
    }
    float s = 0.f;
#pragma unroll
    for (int m = 0; m < 16; ++m) {
        float t = 0.f;
#pragma unroll
        for (int k = 0; k < 16; ++k)
            t = fmaf(sT[(m * 16 + k) * NBL + l], rv[k], t);
        s = fmaf(lv[m], t, s);
    }
    out[idx] = s;
}

// ---------------------------------------------------------------------------
extern "C" void kernel_launch(void* const* d_in, const int* in_sizes, int n_in,
                              void* d_out, int out_size) {
    const float* inputs  = (const float*)d_in[0];
    const float* A_left  = (const float*)d_in[1];
    const float* A_mid   = (const float*)d_in[2];
    const float* A_right = (const float*)d_in[3];
    const float* T_out   = (const float*)d_in[4];
    const int*   pos     = (const int*)d_in[5];

    int Lm2 = in_sizes[2] / 512;          // L-2 = 194
    int L   = Lm2 + 2;                    // 196
    int B   = in_sizes[0] / (2 * L);      // 2048
    int NBL = in_sizes[4] / 256;          // 10

    prep_kernel<<<Lm2, 256>>>(A_mid, Lm2);

    // B/16 chains per block per side -> B/8 blocks total, 128 threads each
    chain_kernel<<<B / 8, 128>>>(inputs, A_left, A_right, pos, B, L);

    int total = B * NBL;
    combine_kernel<<<(total + 255) / 256, 256>>>(T_out, (float*)d_out, B, NBL);
}